// round 2
// baseline (speedup 1.0000x reference)
#include <cuda_runtime.h>

// Problem constants
#define MROWS  8192     // B*S
#define SEQ    1024
#define NFEAT  512
#define HIDDEN 1024
#define NHEAD  8
#define DK     64

// Scratch: static __device__ globals (no runtime allocation anywhere).
__device__ float g_h [(size_t)MROWS * HIDDEN];   // 32 MB
__device__ float g_aw[(size_t)MROWS * NFEAT];    // 16 MB, layout [B][H][S][64]
__device__ float g_v [(size_t)MROWS * NFEAT];    // 16 MB, layout [B][H][S][64]
__device__ float g_x [(size_t)MROWS * NFEAT];    // 16 MB, layout [B][S][F]

__device__ __forceinline__ float ex2(float x) {
    float y;
    asm("ex2.approx.ftz.f32 %0, %1;" : "=f"(y) : "f"(x));
    return y;
}

// Buffer tags so device code resolves scratch globals itself; kernel_launch
// passes only harness pointers (or nullptr).
#define BUF_PTR 0
#define BUF_H   1
#define BUF_AW  2
#define BUF_V   3
#define BUF_X   4

template<int TAG>
__device__ __forceinline__ float* resolve(float* p) {
    if (TAG == BUF_H)  return g_h;
    if (TAG == BUF_AW) return g_aw;
    if (TAG == BUF_V)  return g_v;
    if (TAG == BUF_X)  return g_x;
    return p;
}
template<int TAG>
__device__ __forceinline__ const float* resolve_c(const float* p) {
    if (TAG == BUF_H)  return g_h;
    if (TAG == BUF_AW) return g_aw;
    if (TAG == BUF_V)  return g_v;
    if (TAG == BUF_X)  return g_x;
    return p;
}

// ---------------------------------------------------------------------------
// SGEMM: C[M,N] = op(A[M,K] @ W[K,N] + bias)
// BM=128, BN=64, BK=16, 256 threads, 8x4 per-thread microtile.
// SCATTER: write C to [B][H][S][64] layout (requires BN==64, N==512).
// ---------------------------------------------------------------------------
template<int SRC, int DST, bool RELU, bool SCATTER>
__global__ __launch_bounds__(256)
void gemm_kernel(const float* __restrict__ Ain, const float* __restrict__ W,
                 const float* __restrict__ bias, float* __restrict__ Cout,
                 int K, int N) {
    const float* A = resolve_c<SRC>(Ain);
    float*       C = resolve<DST>(Cout);

    __shared__ __align__(16) float As[16][132];
    __shared__ __align__(16) float Ws[16][68];

    const int tid = threadIdx.x;
    const int tx  = tid & 15;        // N dir: 16 * 4 = 64
    const int ty  = tid >> 4;        // M dir: 16 * 8 = 128
    const int bm  = blockIdx.y << 7;
    const int bn  = blockIdx.x << 6;

    // A tile load mapping: 128 rows x 16 k, 2 float4 per thread
    const int a_row = tid >> 1;            // 0..127
    const int a_k8  = (tid & 1) << 3;      // 0 or 8
    const float* Ap = A + (size_t)(bm + a_row) * K + a_k8;
    // W tile load mapping: 16 rows x 64 n, 1 float4 per thread
    const float* Wp = W + (size_t)ty * N + bn + (tx << 2);

    float acc[8][4];
#pragma unroll
    for (int i = 0; i < 8; i++)
#pragma unroll
        for (int j = 0; j < 4; j++) acc[i][j] = 0.f;

    for (int k0 = 0; k0 < K; k0 += 16) {
        float4 a0 = *(const float4*)(Ap + k0);
        float4 a1 = *(const float4*)(Ap + k0 + 4);
        float4 wv = *(const float4*)(Wp + (size_t)k0 * N);
        As[a_k8 + 0][a_row] = a0.x;
        As[a_k8 + 1][a_row] = a0.y;
        As[a_k8 + 2][a_row] = a0.z;
        As[a_k8 + 3][a_row] = a0.w;
        As[a_k8 + 4][a_row] = a1.x;
        As[a_k8 + 5][a_row] = a1.y;
        As[a_k8 + 6][a_row] = a1.z;
        As[a_k8 + 7][a_row] = a1.w;
        *(float4*)&Ws[ty][tx << 2] = wv;
        __syncthreads();

#pragma unroll
        for (int kk = 0; kk < 16; kk++) {
            float4 x0 = *(const float4*)&As[kk][ty << 3];
            float4 x1 = *(const float4*)&As[kk][(ty << 3) + 4];
            float4 y0 = *(const float4*)&Ws[kk][tx << 2];
            float ar[8] = {x0.x, x0.y, x0.z, x0.w, x1.x, x1.y, x1.z, x1.w};
            float br[4] = {y0.x, y0.y, y0.z, y0.w};
#pragma unroll
            for (int i = 0; i < 8; i++)
#pragma unroll
                for (int j = 0; j < 4; j++)
                    acc[i][j] = fmaf(ar[i], br[j], acc[i][j]);
        }
        __syncthreads();
    }

    float4 bv = *(const float4*)(bias + bn + (tx << 2));
#pragma unroll
    for (int i = 0; i < 8; i++) {
        const int m = bm + (ty << 3) + i;
        float4 cv = make_float4(acc[i][0] + bv.x, acc[i][1] + bv.y,
                                acc[i][2] + bv.z, acc[i][3] + bv.w);
        if (RELU) {
            cv.x = fmaxf(cv.x, 0.f); cv.y = fmaxf(cv.y, 0.f);
            cv.z = fmaxf(cv.z, 0.f); cv.w = fmaxf(cv.w, 0.f);
        }
        if (SCATTER) {
            // n = bn + tx*4; head h = bn/64, d = tx*4
            const int b = m >> 10, s = m & 1023, h = bn >> 6;
            *(float4*)(C + (((size_t)(b * NHEAD + h) * SEQ + s) << 6) + (tx << 2)) = cv;
        } else {
            *(float4*)(C + (size_t)m * N + bn + (tx << 2)) = cv;
        }
    }
}

// ---------------------------------------------------------------------------
// Fused flash attention per (b,h):  g_x[b,s,h*64+d] = softmax(AW AW^T / 8) @ V
// Block: 256 threads, TQ=64 query rows, TK=32 key rows per tile, 32 tiles.
// Qs/Ks transposed [d][idx] for the QK dot; P stored transposed Pt[k][q] so
// PV is 2 conflict-free LDS.128 per 16 FMA. O accumulated as O[d][q] in regs.
// exp folded into log2 domain: Q pre-scaled by log2(e)/8, ex2.approx for exp.
// Reads g_aw / g_v, writes g_x — no pointer arguments needed.
// ---------------------------------------------------------------------------
__global__ __launch_bounds__(256)
void attn_kernel() {
    __shared__ __align__(16) float Qs[64][68];       // [d][q], scaled
    __shared__ __align__(16) float KP[64 * 34];      // Ks[d][k] (stride 34) then Pt[k][q] (stride 68)
    __shared__ __align__(16) float Vs[32 * 68];      // [k][d], natural layout
    __shared__ float m_s[64], l_s[64], scale_s[64];

    const int tid = threadIdx.x;
    const int tx  = tid & 15;
    const int ty  = tid >> 4;
    const int bh  = blockIdx.y;           // 0..63
    const int q0  = blockIdx.x << 6;      // query tile base

    const float* aw = g_aw + ((size_t)bh << 16);   // bh * 1024 * 64
    const float* vp = g_v  + ((size_t)bh << 16);

    const float CSCALE = 0.125f * 1.4426950408889634f;  // (1/sqrt(64)) * log2(e)

    // Load Q tile [64 s][64 d] transposed into Qs[d][s], pre-scaled.
    {
        const int r = tid >> 2;                 // 0..63
#pragma unroll
        for (int i = 0; i < 4; i++) {
            const int d4 = (tid & 3) + (i << 2);
            float4 qv = *(const float4*)(aw + ((size_t)(q0 + r) << 6) + (d4 << 2));
            Qs[(d4 << 2) + 0][r] = qv.x * CSCALE;
            Qs[(d4 << 2) + 1][r] = qv.y * CSCALE;
            Qs[(d4 << 2) + 2][r] = qv.z * CSCALE;
            Qs[(d4 << 2) + 3][r] = qv.w * CSCALE;
        }
    }
    if (tid < 64) { m_s[tid] = -1e30f; l_s[tid] = 0.f; }

    float o[4][4];                         // o[di][qi]: O[d=ty*4+di][q=tx*4+qi]
#pragma unroll
    for (int di = 0; di < 4; di++)
#pragma unroll
        for (int qi = 0; qi < 4; qi++) o[di][qi] = 0.f;

    __syncthreads();

    for (int t = 0; t < 32; t++) {
        const int kb = t << 5;
        // Load K tile [32 k][64 d] transposed into Ks[d][k]; V tile into Vs[k][d].
        {
            const int r   = tid >> 3;           // 0..31
            const int d4a = tid & 7;
#pragma unroll
            for (int i = 0; i < 2; i++) {
                const int d4 = d4a + (i << 3);
                float4 kv = *(const float4*)(aw + ((size_t)(kb + r) << 6) + (d4 << 2));
                KP[((d4 << 2) + 0) * 34 + r] = kv.x;
                KP[((d4 << 2) + 1) * 34 + r] = kv.y;
                KP[((d4 << 2) + 2) * 34 + r] = kv.z;
                KP[((d4 << 2) + 3) * 34 + r] = kv.w;
                float4 vv = *(const float4*)(vp + ((size_t)(kb + r) << 6) + (d4 << 2));
                *(float4*)&Vs[r * 68 + (d4 << 2)] = vv;
            }
        }
        __syncthreads();

        // S tile: s[qi][j] for q = ty*4+qi, k = tx*2+j  (log2 units, pre-scaled)
        float s[4][2] = {{0.f,0.f},{0.f,0.f},{0.f,0.f},{0.f,0.f}};
#pragma unroll 16
        for (int d = 0; d < 64; d++) {
            float4 qv = *(const float4*)&Qs[d][ty << 2];
            float2 kv = *(const float2*)&KP[d * 34 + (tx << 1)];
            s[0][0] = fmaf(qv.x, kv.x, s[0][0]); s[0][1] = fmaf(qv.x, kv.y, s[0][1]);
            s[1][0] = fmaf(qv.y, kv.x, s[1][0]); s[1][1] = fmaf(qv.y, kv.y, s[1][1]);
            s[2][0] = fmaf(qv.z, kv.x, s[2][0]); s[2][1] = fmaf(qv.z, kv.y, s[2][1]);
            s[3][0] = fmaf(qv.w, kv.x, s[3][0]); s[3][1] = fmaf(qv.w, kv.y, s[3][1]);
        }

        // Row max across the 16 tx lanes (xor<16 keeps each half-warp = one ty)
        float pm[4];
#pragma unroll
        for (int qi = 0; qi < 4; qi++) pm[qi] = fmaxf(s[qi][0], s[qi][1]);
#pragma unroll
        for (int off = 8; off > 0; off >>= 1)
#pragma unroll
            for (int qi = 0; qi < 4; qi++)
                pm[qi] = fmaxf(pm[qi], __shfl_xor_sync(0xffffffffu, pm[qi], off));
        if (tx == 0) {
#pragma unroll
            for (int qi = 0; qi < 4; qi++) {
                const int row = (ty << 2) + qi;
                const float mo = m_s[row];
                const float mn = fmaxf(mo, pm[qi]);
                scale_s[row] = ex2(mo - mn);
                m_s[row] = mn;
            }
        }
        __syncthreads();   // QK reads of Ks done; m_s/scale_s visible

        // P = exp2(s - m); store transposed Pt[k][q]; accumulate row sums
        float rs[4];
#pragma unroll
        for (int qi = 0; qi < 4; qi++) {
            const int row = (ty << 2) + qi;
            const float mrow = m_s[row];
            const float p0 = ex2(s[qi][0] - mrow);
            const float p1 = ex2(s[qi][1] - mrow);
            KP[((tx << 1) + 0) * 68 + row] = p0;   // Pt[k][q]
            KP[((tx << 1) + 1) * 68 + row] = p1;
            rs[qi] = p0 + p1;
        }
#pragma unroll
        for (int off = 8; off > 0; off >>= 1)
#pragma unroll
            for (int qi = 0; qi < 4; qi++)
                rs[qi] += __shfl_xor_sync(0xffffffffu, rs[qi], off);
        if (tx == 0) {
#pragma unroll
            for (int qi = 0; qi < 4; qi++) {
                const int row = (ty << 2) + qi;
                l_s[row] = l_s[row] * scale_s[row] + rs[qi];
            }
        }
        __syncthreads();   // Pt fully written

        // Rescale O, then O += Pt^T @ Vs
        float sc[4];
#pragma unroll
        for (int qi = 0; qi < 4; qi++) sc[qi] = scale_s[(tx << 2) + qi];
#pragma unroll
        for (int di = 0; di < 4; di++)
#pragma unroll
            for (int qi = 0; qi < 4; qi++) o[di][qi] *= sc[qi];

#pragma unroll
        for (int k = 0; k < 32; k++) {
            float4 pp = *(const float4*)&KP[k * 68 + (tx << 2)];  // P[q=tx*4..][k]
            float4 vv = *(const float4*)&Vs[k * 68 + (ty << 2)];  // V[k][d=ty*4..]
            o[0][0] = fmaf(vv.x, pp.x, o[0][0]); o[0][1] = fmaf(vv.x, pp.y, o[0][1]);
            o[0][2] = fmaf(vv.x, pp.z, o[0][2]); o[0][3] = fmaf(vv.x, pp.w, o[0][3]);
            o[1][0] = fmaf(vv.y, pp.x, o[1][0]); o[1][1] = fmaf(vv.y, pp.y, o[1][1]);
            o[1][2] = fmaf(vv.y, pp.z, o[1][2]); o[1][3] = fmaf(vv.y, pp.w, o[1][3]);
            o[2][0] = fmaf(vv.z, pp.x, o[2][0]); o[2][1] = fmaf(vv.z, pp.y, o[2][1]);
            o[2][2] = fmaf(vv.z, pp.z, o[2][2]); o[2][3] = fmaf(vv.z, pp.w, o[2][3]);
            o[3][0] = fmaf(vv.w, pp.x, o[3][0]); o[3][1] = fmaf(vv.w, pp.y, o[3][1]);
            o[3][2] = fmaf(vv.w, pp.z, o[3][2]); o[3][3] = fmaf(vv.w, pp.w, o[3][3]);
        }
        __syncthreads();   // done with Ks/Pt/Vs; safe to reload next tile
    }

    // Normalize and write g_x[b][s][h*64+d]
    const int bb = bh >> 3, hh = bh & 7;
    float* xp = g_x + (size_t)(bb * SEQ + q0) * NFEAT + (hh << 6) + (ty << 2);
#pragma unroll
    for (int qi = 0; qi < 4; qi++) {
        const int row = (tx << 2) + qi;
        const float inv = 1.f / l_s[row];
        float4 ov = make_float4(o[0][qi] * inv, o[1][qi] * inv,
                                o[2][qi] * inv, o[3][qi] * inv);
        *(float4*)(xp + (size_t)row * NFEAT) = ov;
    }
}

// ---------------------------------------------------------------------------
// Launch: kernel launches ONLY — no runtime API calls of any kind.
// ---------------------------------------------------------------------------
extern "C" void kernel_launch(void* const* d_in, const int* in_sizes, int n_in,
                              void* d_out, int out_size) {
    (void)in_sizes; (void)n_in; (void)out_size;
    const float* q   = (const float*)d_in[0];
    // d_in[1] = key_t (unused by synthesizer attention)
    const float* val = (const float*)d_in[2];
    const float* w1  = (const float*)d_in[3];
    const float* b1  = (const float*)d_in[4];
    const float* w2  = (const float*)d_in[5];
    const float* b2  = (const float*)d_in[6];
    const float* wv  = (const float*)d_in[7];
    const float* bv  = (const float*)d_in[8];
    const float* wo  = (const float*)d_in[9];
    const float* bo  = (const float*)d_in[10];
    float* out = (float*)d_out;

    const dim3 blk(256);
    // 1) g_h = relu(q @ w1 + b1)             [8192,512]x[512,1024]
    gemm_kernel<BUF_PTR, BUF_H,  true,  false>
        <<<dim3(HIDDEN / 64, MROWS / 128), blk>>>(q,   w1, b1, nullptr, NFEAT,  HIDDEN);
    // 2) g_aw = g_h @ w2 + b2 -> [B,H,S,64]  [8192,1024]x[1024,512]
    gemm_kernel<BUF_H,   BUF_AW, false, true >
        <<<dim3(NFEAT  / 64, MROWS / 128), blk>>>(nullptr, w2, b2, nullptr, HIDDEN, NFEAT);
    // 3) g_v = value @ wv + bv -> [B,H,S,64]
    gemm_kernel<BUF_PTR, BUF_V,  false, true >
        <<<dim3(NFEAT  / 64, MROWS / 128), blk>>>(val, wv, bv, nullptr, NFEAT,  NFEAT);
    // 4) g_x = softmax(g_aw g_aw^T / 8) @ g_v -> [B,S,F]
    attn_kernel<<<dim3(SEQ / 64, NHEAD * 8), blk>>>();
    // 5) out = g_x @ wo + bo
    gemm_kernel<BUF_X,   BUF_PTR, false, false>
        <<<dim3(NFEAT  / 64, MROWS / 128), blk>>>(nullptr, wo, bo, out, NFEAT,  NFEAT);
}

// round 6
// speedup vs baseline: 1.1784x; 1.1784x over previous
#include <cuda_runtime.h>
#include <cstdint>

// Problem constants
#define MROWS  8192     // B*S
#define SEQ    1024
#define NFEAT  512
#define HIDDEN 1024
#define NHEAD  8

// ---------------------------------------------------------------------------
// Scratch: static __device__ globals (no runtime allocation anywhere).
// ---------------------------------------------------------------------------
__device__ float g_h [(size_t)MROWS * HIDDEN];   // 32 MB
__device__ float g_aw[(size_t)MROWS * NFEAT];    // 16 MB, [B][H][S][64]
__device__ float g_v [(size_t)MROWS * NFEAT];    // 16 MB, [B][H][S][64]
__device__ float g_x [(size_t)MROWS * NFEAT];    // 16 MB, [B][S][F]

#define BUF_PTR 0
#define BUF_H   1
#define BUF_AW  2
#define BUF_V   3
#define BUF_X   4

template<int TAG> __device__ __forceinline__ float* resolve(float* p) {
    if (TAG == BUF_H)  return g_h;
    if (TAG == BUF_AW) return g_aw;
    if (TAG == BUF_V)  return g_v;
    if (TAG == BUF_X)  return g_x;
    return p;
}
template<int TAG> __device__ __forceinline__ const float* resolve_c(const float* p) {
    if (TAG == BUF_H)  return g_h;
    if (TAG == BUF_AW) return g_aw;
    if (TAG == BUF_V)  return g_v;
    if (TAG == BUF_X)  return g_x;
    return p;
}

__device__ __forceinline__ float ex2(float x) {
    float y;
    asm("ex2.approx.ftz.f32 %0, %1;" : "=f"(y) : "f"(x));
    return y;
}

// Round fp32 -> tf32 (result is an fp32 bit-pattern with 10-bit mantissa).
__device__ __forceinline__ uint32_t f2tf32(float x) {
    uint32_t r;
    asm("cvt.rna.tf32.f32 %0, %1;" : "=r"(r) : "f"(x));
    return r;
}

// tf32 mma: D[16,8] += A[16,8] * B[8,8]  (row.col), fp32 accum.
// A regs: a0=(r,k) a1=(r+8,k) a2=(r,k+4) a3=(r+8,k+4), r=lane/4, k=lane%4
// B regs: b0=(k,n)  b1=(k+4,n), n=lane/4
// C regs: c0=(r,2c) c1=(r,2c+1) c2=(r+8,2c) c3=(r+8,2c+1), c=lane%4
__device__ __forceinline__ void mma_tf32(float* d, const uint32_t* a, const uint32_t* b) {
    asm volatile(
        "mma.sync.aligned.m16n8k8.row.col.f32.tf32.tf32.f32 "
        "{%0,%1,%2,%3}, {%4,%5,%6,%7}, {%8,%9}, {%0,%1,%2,%3};"
        : "+f"(d[0]), "+f"(d[1]), "+f"(d[2]), "+f"(d[3])
        : "r"(a[0]), "r"(a[1]), "r"(a[2]), "r"(a[3]), "r"(b[0]), "r"(b[1]));
}

// ---------------------------------------------------------------------------
// 3xTF32 tensor-core GEMM: C[M,N] = op(A[M,K] @ W[K,N] + bias)
// Each operand split hi/lo at fragment load; D += Alo*Bhi + Ahi*Blo + Ahi*Bhi
// recovers ~fp32 accuracy (dropped lo*lo term ~2^-22).
// CTA tile 128x128, K-chunk 32. 8 warps as 2(M) x 4(N); warp tile 64x32.
// Single SMEM stage + register prefetch of next chunk. W used directly
// ([K][N] IS the k-major B operand). SCATTER writes C to [B][H][S][64].
// ---------------------------------------------------------------------------
template<int SRCA, int DSTT, bool RELU, bool SCATTER>
__global__ __launch_bounds__(256)
void gemm_mma(const float* __restrict__ Ain, const float* __restrict__ W,
              const float* __restrict__ bias, float* __restrict__ Cout,
              int K, int N) {
    const float* A = resolve_c<SRCA>(Ain);
    float*       C = resolve<DSTT>(Cout);

    __shared__ __align__(16) float As[128 * 36];   // [m][k], stride 36
    __shared__ __align__(16) float Bs[32 * 136];   // [k][n], stride 136

    const int tid  = threadIdx.x;
    const int wid  = tid >> 5, lane = tid & 31;
    const int wm   = (wid & 1) << 6;      // warp M base: 0/64
    const int wn   = (wid >> 1) << 5;     // warp N base: 0/32/64/96
    const int lr   = lane >> 2;           // 0..7
    const int lk   = lane & 3;            // 0..3
    const int bm = blockIdx.y << 7, bn = blockIdx.x << 7;

    float acc[4][4][4];
#pragma unroll
    for (int mi = 0; mi < 4; mi++)
#pragma unroll
        for (int ni = 0; ni < 4; ni++)
#pragma unroll
            for (int e = 0; e < 4; e++) acc[mi][ni][e] = 0.f;

    const int nchunk = K >> 5;
    // Prefetch chunk 0. A: 128x32 (8 f4/row); B: 32x128 (32 f4/row).
    float4 pa[4], pb[4];
#pragma unroll
    for (int i = 0; i < 4; i++) {
        const int ia = tid + (i << 8), ra = ia >> 3, ca = ia & 7;
        pa[i] = *(const float4*)(A + (size_t)(bm + ra) * K + (ca << 2));
        const int ib = tid + (i << 8), rb = ib >> 5, cb = ib & 31;
        pb[i] = *(const float4*)(W + (size_t)rb * N + bn + (cb << 2));
    }

    for (int c = 0; c < nchunk; c++) {
#pragma unroll
        for (int i = 0; i < 4; i++) {
            const int ia = tid + (i << 8), ra = ia >> 3, ca = ia & 7;
            *(float4*)&As[ra * 36 + (ca << 2)] = pa[i];
            const int ib = tid + (i << 8), rb = ib >> 5, cb = ib & 31;
            *(float4*)&Bs[rb * 136 + (cb << 2)] = pb[i];
        }
        __syncthreads();
        if (c + 1 < nchunk) {
            const int k0 = (c + 1) << 5;
#pragma unroll
            for (int i = 0; i < 4; i++) {
                const int ia = tid + (i << 8), ra = ia >> 3, ca = ia & 7;
                pa[i] = *(const float4*)(A + (size_t)(bm + ra) * K + k0 + (ca << 2));
                const int ib = tid + (i << 8), rb = ib >> 5, cb = ib & 31;
                pb[i] = *(const float4*)(W + (size_t)(k0 + rb) * N + bn + (cb << 2));
            }
        }
#pragma unroll
        for (int ks = 0; ks < 4; ks++) {
            const int kk = (ks << 3) + lk;
            uint32_t ah[4][4], al[4][4], bh[4][2], bl[4][2];
#pragma unroll
            for (int mi = 0; mi < 4; mi++) {
                const int r = wm + (mi << 4) + lr;
                const float v0 = As[r * 36 + kk];
                const float v1 = As[(r + 8) * 36 + kk];
                const float v2 = As[r * 36 + kk + 4];
                const float v3 = As[(r + 8) * 36 + kk + 4];
                ah[mi][0] = f2tf32(v0); al[mi][0] = f2tf32(v0 - __uint_as_float(ah[mi][0]));
                ah[mi][1] = f2tf32(v1); al[mi][1] = f2tf32(v1 - __uint_as_float(ah[mi][1]));
                ah[mi][2] = f2tf32(v2); al[mi][2] = f2tf32(v2 - __uint_as_float(ah[mi][2]));
                ah[mi][3] = f2tf32(v3); al[mi][3] = f2tf32(v3 - __uint_as_float(ah[mi][3]));
            }
#pragma unroll
            for (int ni = 0; ni < 4; ni++) {
                const int nc = wn + (ni << 3) + lr;
                const float u0 = Bs[kk * 136 + nc];
                const float u1 = Bs[(kk + 4) * 136 + nc];
                bh[ni][0] = f2tf32(u0); bl[ni][0] = f2tf32(u0 - __uint_as_float(bh[ni][0]));
                bh[ni][1] = f2tf32(u1); bl[ni][1] = f2tf32(u1 - __uint_as_float(bh[ni][1]));
            }
            // Small terms first, dominant hi*hi last.
#pragma unroll
            for (int mi = 0; mi < 4; mi++)
#pragma unroll
                for (int ni = 0; ni < 4; ni++)
                    mma_tf32(acc[mi][ni], al[mi], bh[ni]);
#pragma unroll
            for (int mi = 0; mi < 4; mi++)
#pragma unroll
                for (int ni = 0; ni < 4; ni++)
                    mma_tf32(acc[mi][ni], ah[mi], bl[ni]);
#pragma unroll
            for (int mi = 0; mi < 4; mi++)
#pragma unroll
                for (int ni = 0; ni < 4; ni++)
                    mma_tf32(acc[mi][ni], ah[mi], bh[ni]);
        }
        __syncthreads();
    }

    // Epilogue: direct float2 stores, bias + optional ReLU + optional scatter.
    const int lc2 = (lane & 3) << 1;
#pragma unroll
    for (int mi = 0; mi < 4; mi++) {
#pragma unroll
        for (int ni = 0; ni < 4; ni++) {
            const int col = bn + wn + (ni << 3) + lc2;
            const float bx = bias[col], by = bias[col + 1];
#pragma unroll
            for (int half = 0; half < 2; half++) {
                const int m = bm + wm + (mi << 4) + lr + (half << 3);
                float vx = acc[mi][ni][2 * half + 0] + bx;
                float vy = acc[mi][ni][2 * half + 1] + by;
                if (RELU) { vx = fmaxf(vx, 0.f); vy = fmaxf(vy, 0.f); }
                if (SCATTER) {
                    const int hh = col >> 6, d = col & 63;
                    const int bb_ = m >> 10, s = m & 1023;
                    *(float2*)(C + (((size_t)(bb_ * NHEAD + hh) * SEQ + s) << 6) + d)
                        = make_float2(vx, vy);
                } else {
                    *(float2*)(C + (size_t)m * N + col) = make_float2(vx, vy);
                }
            }
        }
    }
}

// ---------------------------------------------------------------------------
// Fused flash attention per (b,h) — fp32 version (passed @583us in R2).
// ---------------------------------------------------------------------------
__global__ __launch_bounds__(256)
void attn_kernel() {
    __shared__ __align__(16) float Qs[64][68];
    __shared__ __align__(16) float KP[64 * 34];
    __shared__ __align__(16) float Vs[32 * 68];
    __shared__ float m_s[64], l_s[64], scale_s[64];

    const int tid = threadIdx.x;
    const int tx  = tid & 15;
    const int ty  = tid >> 4;
    const int bh  = blockIdx.y;
    const int q0  = blockIdx.x << 6;

    const float* aw = g_aw + ((size_t)bh << 16);
    const float* vp = g_v  + ((size_t)bh << 16);
    const float CSCALE = 0.125f * 1.4426950408889634f;

    {
        const int r = tid >> 2;
#pragma unroll
        for (int i = 0; i < 4; i++) {
            const int d4 = (tid & 3) + (i << 2);
            float4 qv = *(const float4*)(aw + ((size_t)(q0 + r) << 6) + (d4 << 2));
            Qs[(d4 << 2) + 0][r] = qv.x * CSCALE;
            Qs[(d4 << 2) + 1][r] = qv.y * CSCALE;
            Qs[(d4 << 2) + 2][r] = qv.z * CSCALE;
            Qs[(d4 << 2) + 3][r] = qv.w * CSCALE;
        }
    }
    if (tid < 64) { m_s[tid] = -1e30f; l_s[tid] = 0.f; }

    float o[4][4];
#pragma unroll
    for (int di = 0; di < 4; di++)
#pragma unroll
        for (int qi = 0; qi < 4; qi++) o[di][qi] = 0.f;

    __syncthreads();

    for (int t = 0; t < 32; t++) {
        const int kb = t << 5;
        {
            const int r   = tid >> 3;
            const int d4a = tid & 7;
#pragma unroll
            for (int i = 0; i < 2; i++) {
                const int d4 = d4a + (i << 3);
                float4 kv = *(const float4*)(aw + ((size_t)(kb + r) << 6) + (d4 << 2));
                KP[((d4 << 2) + 0) * 34 + r] = kv.x;
                KP[((d4 << 2) + 1) * 34 + r] = kv.y;
                KP[((d4 << 2) + 2) * 34 + r] = kv.z;
                KP[((d4 << 2) + 3) * 34 + r] = kv.w;
                float4 vv = *(const float4*)(vp + ((size_t)(kb + r) << 6) + (d4 << 2));
                *(float4*)&Vs[r * 68 + (d4 << 2)] = vv;
            }
        }
        __syncthreads();

        float s[4][2] = {{0.f,0.f},{0.f,0.f},{0.f,0.f},{0.f,0.f}};
#pragma unroll 16
        for (int d = 0; d < 64; d++) {
            float4 qv = *(const float4*)&Qs[d][ty << 2];
            float2 kv = *(const float2*)&KP[d * 34 + (tx << 1)];
            s[0][0] = fmaf(qv.x, kv.x, s[0][0]); s[0][1] = fmaf(qv.x, kv.y, s[0][1]);
            s[1][0] = fmaf(qv.y, kv.x, s[1][0]); s[1][1] = fmaf(qv.y, kv.y, s[1][1]);
            s[2][0] = fmaf(qv.z, kv.x, s[2][0]); s[2][1] = fmaf(qv.z, kv.y, s[2][1]);
            s[3][0] = fmaf(qv.w, kv.x, s[3][0]); s[3][1] = fmaf(qv.w, kv.y, s[3][1]);
        }

        float pm[4];
#pragma unroll
        for (int qi = 0; qi < 4; qi++) pm[qi] = fmaxf(s[qi][0], s[qi][1]);
#pragma unroll
        for (int off = 8; off > 0; off >>= 1)
#pragma unroll
            for (int qi = 0; qi < 4; qi++)
                pm[qi] = fmaxf(pm[qi], __shfl_xor_sync(0xffffffffu, pm[qi], off));
        if (tx == 0) {
#pragma unroll
            for (int qi = 0; qi < 4; qi++) {
                const int row = (ty << 2) + qi;
                const float mo = m_s[row];
                const float mn = fmaxf(mo, pm[qi]);
                scale_s[row] = ex2(mo - mn);
                m_s[row] = mn;
            }
        }
        __syncthreads();

        float rs[4];
#pragma unroll
        for (int qi = 0; qi < 4; qi++) {
            const int row = (ty << 2) + qi;
            const float mrow = m_s[row];
            const float p0 = ex2(s[qi][0] - mrow);
            const float p1 = ex2(s[qi][1] - mrow);
            KP[((tx << 1) + 0) * 68 + row] = p0;
            KP[((tx << 1) + 1) * 68 + row] = p1;
            rs[qi] = p0 + p1;
        }
#pragma unroll
        for (int off = 8; off > 0; off >>= 1)
#pragma unroll
            for (int qi = 0; qi < 4; qi++)
                rs[qi] += __shfl_xor_sync(0xffffffffu, rs[qi], off);
        if (tx == 0) {
#pragma unroll
            for (int qi = 0; qi < 4; qi++) {
                const int row = (ty << 2) + qi;
                l_s[row] = l_s[row] * scale_s[row] + rs[qi];
            }
        }
        __syncthreads();

        float sc[4];
#pragma unroll
        for (int qi = 0; qi < 4; qi++) sc[qi] = scale_s[(tx << 2) + qi];
#pragma unroll
        for (int di = 0; di < 4; di++)
#pragma unroll
            for (int qi = 0; qi < 4; qi++) o[di][qi] *= sc[qi];

#pragma unroll
        for (int k = 0; k < 32; k++) {
            float4 pp = *(const float4*)&KP[k * 68 + (tx << 2)];
            float4 vv = *(const float4*)&Vs[k * 68 + (ty << 2)];
            o[0][0] = fmaf(vv.x, pp.x, o[0][0]); o[0][1] = fmaf(vv.x, pp.y, o[0][1]);
            o[0][2] = fmaf(vv.x, pp.z, o[0][2]); o[0][3] = fmaf(vv.x, pp.w, o[0][3]);
            o[1][0] = fmaf(vv.y, pp.x, o[1][0]); o[1][1] = fmaf(vv.y, pp.y, o[1][1]);
            o[1][2] = fmaf(vv.y, pp.z, o[1][2]); o[1][3] = fmaf(vv.y, pp.w, o[1][3]);
            o[2][0] = fmaf(vv.z, pp.x, o[2][0]); o[2][1] = fmaf(vv.z, pp.y, o[2][1]);
            o[2][2] = fmaf(vv.z, pp.z, o[2][2]); o[2][3] = fmaf(vv.z, pp.w, o[2][3]);
            o[3][0] = fmaf(vv.w, pp.x, o[3][0]); o[3][1] = fmaf(vv.w, pp.y, o[3][1]);
            o[3][2] = fmaf(vv.w, pp.z, o[3][2]); o[3][3] = fmaf(vv.w, pp.w, o[3][3]);
        }
        __syncthreads();
    }

    const int bb = bh >> 3, hh = bh & 7;
    float* xp = g_x + (size_t)(bb * SEQ + q0) * NFEAT + (hh << 6) + (ty << 2);
#pragma unroll
    for (int qi = 0; qi < 4; qi++) {
        const int row = (tx << 2) + qi;
        const float inv = 1.f / l_s[row];
        float4 ov = make_float4(o[0][qi] * inv, o[1][qi] * inv,
                                o[2][qi] * inv, o[3][qi] * inv);
        *(float4*)(xp + (size_t)row * NFEAT) = ov;
    }
}

// ---------------------------------------------------------------------------
// Launch: kernel launches ONLY.
// ---------------------------------------------------------------------------
extern "C" void kernel_launch(void* const* d_in, const int* in_sizes, int n_in,
                              void* d_out, int out_size) {
    (void)in_sizes; (void)n_in; (void)out_size;
    const float* q   = (const float*)d_in[0];
    // d_in[1] = key_t (unused)
    const float* val = (const float*)d_in[2];
    const float* w1  = (const float*)d_in[3];
    const float* b1  = (const float*)d_in[4];
    const float* w2  = (const float*)d_in[5];
    const float* b2  = (const float*)d_in[6];
    const float* wv  = (const float*)d_in[7];
    const float* bv  = (const float*)d_in[8];
    const float* wo  = (const float*)d_in[9];
    const float* bo  = (const float*)d_in[10];
    float* out = (float*)d_out;

    const dim3 blk(256);
    // 1) g_h = relu(q @ w1 + b1)
    gemm_mma<BUF_PTR, BUF_H,  true,  false>
        <<<dim3(HIDDEN / 128, MROWS / 128), blk>>>(q,   w1, b1, nullptr, NFEAT,  HIDDEN);
    // 2) g_aw = g_h @ w2 + b2 -> [B,H,S,64]
    gemm_mma<BUF_H,   BUF_AW, false, true >
        <<<dim3(NFEAT  / 128, MROWS / 128), blk>>>(nullptr, w2, b2, nullptr, HIDDEN, NFEAT);
    // 3) g_v = value @ wv + bv -> [B,H,S,64]
    gemm_mma<BUF_PTR, BUF_V,  false, true >
        <<<dim3(NFEAT  / 128, MROWS / 128), blk>>>(val, wv, bv, nullptr, NFEAT,  NFEAT);
    // 4) g_x = softmax(g_aw g_aw^T / 8) @ g_v -> [B,S,F]
    attn_kernel<<<dim3(SEQ / 64, NHEAD * 8), blk>>>();
    // 5) out = g_x @ wo + bo
    gemm_mma<BUF_X,   BUF_PTR, false, false>
        <<<dim3(NFEAT  / 128, MROWS / 128), blk>>>(nullptr, wo, bo, out, NFEAT,  NFEAT);
}